// round 15
// baseline (speedup 1.0000x reference)
#include <cuda_runtime.h>
#include <cuda_fp16.h>
#include <cstdint>

#define TOKENS 8192
#define DIM    1024
#define NE     8
#define HID    2730
#define HP     2816
#define KH     2752
#define NPAIR  (TOKENS*2)
#define HROWS  (NPAIR + 256)

#define SWZ(o) ((o) ^ (((o) >> 3) & 0x70))

#define BM1 128
#define ST1 32768   // gemm1 stage: Ah 0 (16K), W1h 16384 (8K), W3h 24576 (8K)
#define BM2 256
#define ST2 49152   // gemm2 stage: Ah 0 (32K), Bh 32768 (16K)
#define NSTG 3

// ---------------- device scratch ----------------
__device__ int   g_count[NE];
__device__ int   g_off[NE];
__device__ int   g_tokens[NE][TOKENS];
__device__ float g_wts[NE][TOKENS];
__device__ float g_probsum[NE];

__device__ __half g_XH[TOKENS*DIM];
__device__ __half g_W1H[NE*HP*DIM];
__device__ __half g_W3H[NE*HP*DIM];
__device__ __half g_W2H[NE*DIM*HP];
__device__ __half g_HH[(size_t)HROWS*HP];

// ---------------- helpers ----------------
__device__ __forceinline__ uint32_t s2u(const void* p) {
    uint32_t a;
    asm("{ .reg .u64 t; cvta.to.shared.u64 t, %1; cvt.u32.u64 %0, t; }" : "=r"(a) : "l"(p));
    return a;
}
__device__ __forceinline__ void cpa16(uint32_t dst, const void* src) {
    asm volatile("cp.async.cg.shared.global [%0], [%1], 16;" :: "r"(dst), "l"(src));
}
__device__ __forceinline__ void cp_commit() {
    asm volatile("cp.async.commit_group;" ::: "memory");
}
__device__ __forceinline__ void cp_wait2() {
    asm volatile("cp.async.wait_group 2;" ::: "memory");
}
__device__ __forceinline__ void ldm4(uint32_t* r, uint32_t addr) {
    asm volatile("ldmatrix.sync.aligned.m8n8.x4.shared.b16 {%0,%1,%2,%3}, [%4];"
                 : "=r"(r[0]), "=r"(r[1]), "=r"(r[2]), "=r"(r[3]) : "r"(addr));
}
__device__ __forceinline__ void mma16816(float* c, const uint32_t* a, const uint32_t* b) {
    asm volatile("mma.sync.aligned.m16n8k16.row.col.f32.f16.f16.f32 "
                 "{%0,%1,%2,%3}, {%4,%5,%6,%7}, {%8,%9}, {%0,%1,%2,%3};"
                 : "+f"(c[0]), "+f"(c[1]), "+f"(c[2]), "+f"(c[3])
                 : "r"(a[0]), "r"(a[1]), "r"(a[2]), "r"(a[3]), "r"(b[0]), "r"(b[1]));
}
__device__ __forceinline__ uint32_t pkh(__half a, __half b) {
    return ((uint32_t)__half_as_ushort(b) << 16) | (uint32_t)__half_as_ushort(a);
}
__device__ __forceinline__ void redadd(float* p, float v) {
    asm volatile("red.global.add.f32 [%0], %1;" :: "l"(p), "f"(v) : "memory");
}
__device__ __forceinline__ uint2 round4h(float4 v) {
    return make_uint2(pkh(__float2half(v.x), __float2half(v.y)),
                      pkh(__float2half(v.z), __float2half(v.w)));
}

// ---------------- small kernels ----------------
__global__ void reset_kernel() {
    if (threadIdx.x < NE) {
        g_count[threadIdx.x] = 0;
        g_probsum[threadIdx.x] = 0.0f;
    }
}

__global__ void zeroout_kernel(float* __restrict__ out, int n) {
    int i = blockIdx.x * blockDim.x + threadIdx.x;
    if (i < n) out[i] = 0.0f;
}

__global__ void convw13_kernel(const float* __restrict__ w1, const float* __restrict__ w3) {
    int i = blockIdx.x * 256 + threadIdx.x;
    int c4   = i & (DIM / 4 - 1);
    int rowe = i >> 8;
    int row  = rowe % HP;
    int e    = rowe / HP;
    float4 v1 = make_float4(0,0,0,0), v3 = make_float4(0,0,0,0);
    if (row < HID) {
        size_t si = (((size_t)e * HID + row) * DIM) / 4 + c4;
        v1 = ((const float4*)w1)[si];
        v3 = ((const float4*)w3)[si];
    }
    ((uint2*)g_W1H)[i] = round4h(v1);
    ((uint2*)g_W3H)[i] = round4h(v3);
}

__global__ void convw2_kernel(const float* __restrict__ w2) {
    int i = blockIdx.x * 256 + threadIdx.x;
    int c4   = i % (HP / 4);
    int rowd = i / (HP / 4);
    int col = c4 * 4;
    float4 v = make_float4(0,0,0,0);
    const float* src = w2 + (size_t)rowd * HID + col;
    if (col + 3 < HID) {
        v.x = src[0]; v.y = src[1]; v.z = src[2]; v.w = src[3];
    } else if (col < HID) {
        v.x = src[0];
        if (col + 1 < HID) v.y = src[1];
    }
    ((uint2*)g_W2H)[i] = round4h(v);
}

// router + inline x->fp16 convert
__global__ void router_kernel(const float* __restrict__ x, const float* __restrict__ gw) {
    int warp = (blockIdx.x * blockDim.x + threadIdx.x) >> 5;
    int lane = threadIdx.x & 31;
    if (warp >= TOKENS) return;
    const float* xr = x + (size_t)warp * DIM;
    __half* xh = g_XH + (size_t)warp * DIM;
    float acc[NE];
#pragma unroll
    for (int e = 0; e < NE; e++) acc[e] = 0.0f;
    for (int i = lane; i < DIM; i += 32) {
        float xv = xr[i];
        xh[i] = __float2half(xv);
#pragma unroll
        for (int e = 0; e < NE; e++) acc[e] = fmaf(xv, gw[e * DIM + i], acc[e]);
    }
#pragma unroll
    for (int e = 0; e < NE; e++)
#pragma unroll
        for (int o = 16; o; o >>= 1) acc[e] += __shfl_xor_sync(0xffffffffu, acc[e], o);
    if (lane == 0) {
        float m = acc[0];
#pragma unroll
        for (int e = 1; e < NE; e++) m = fmaxf(m, acc[e]);
        float p[NE]; float s = 0.0f;
#pragma unroll
        for (int e = 0; e < NE; e++) { p[e] = __expf(acc[e] - m); s += p[e]; }
        float inv = 1.0f / s;
#pragma unroll
        for (int e = 0; e < NE; e++) p[e] *= inv;
        int i0 = 0;
#pragma unroll
        for (int e = 1; e < NE; e++) if (p[e] > p[i0]) i0 = e;
        int i1 = (i0 == 0) ? 1 : 0;
#pragma unroll
        for (int e = 0; e < NE; e++) if (e != i0 && p[e] > p[i1]) i1 = e;
        float s2 = p[i0] + p[i1];
        int pos0 = atomicAdd(&g_count[i0], 1);
        g_tokens[i0][pos0] = warp; g_wts[i0][pos0] = p[i0] / s2;
        int pos1 = atomicAdd(&g_count[i1], 1);
        g_tokens[i1][pos1] = warp; g_wts[i1][pos1] = p[i1] / s2;
#pragma unroll
        for (int e = 0; e < NE; e++) atomicAdd(&g_probsum[e], p[e]);
    }
}

__global__ void scan_kernel() {
    if (threadIdx.x == 0) {
        int s = 0;
#pragma unroll
        for (int e = 0; e < NE; e++) { g_off[e] = s; s += g_count[e]; }
    }
}

__global__ void aux_kernel(float* __restrict__ out, int out_size) {
    if (threadIdx.x == 0 && blockIdx.x == 0) {
        float s = 0.0f;
#pragma unroll
        for (int e = 0; e < NE; e++) {
            float tpe = g_probsum[e] / (float)TOKENS;
            float d = tpe - (1.0f / NE);
            s += d * d;
        }
        if (out_size > TOKENS * DIM) out[TOKENS * DIM] = 0.01f * (s / (float)NE);
    }
}

// ---------------- GEMM1: CTA 128x64, warp 32x32 dual, fp16 1-pass ----------------
__global__ __launch_bounds__(256, 2) void gemm1_kernel() {
    int e = blockIdx.z;
    int cnt = g_count[e];
    int m0 = blockIdx.y * BM1;
    if (m0 >= cnt) return;
    int n0 = blockIdx.x * 64;

    extern __shared__ char smraw[];
    uint32_t smb = s2u(smraw);
    int tid = threadIdx.x, wid = tid >> 5, lane = tid & 31;

    int rA = tid >> 3, c16 = tid & 7;
    uint32_t dstA[4], aoff[4];
#pragma unroll
    for (int i = 0; i < 4; i++) {
        int r = rA + 32 * i;
        dstA[i] = SWZ((uint32_t)(r * 128 + c16 * 16));
        int mi = m0 + r; if (mi >= cnt) mi = cnt - 1;
        aoff[i] = (uint32_t)((g_tokens[e][mi] * DIM + c16 * 8) * 2);
    }
    uint32_t dstB[2], boff[2];
#pragma unroll
    for (int i = 0; i < 2; i++) {
        int r = rA + 32 * i;
        dstB[i] = SWZ((uint32_t)(r * 128 + c16 * 16));
        boff[i] = (uint32_t)(((e * HP + n0 + r) * DIM + c16 * 8) * 2);
    }

    auto load = [&](int kc, int s) {
        uint32_t base = smb + s * ST1;
        uint32_t ko = (uint32_t)kc * 128;
#pragma unroll
        for (int i = 0; i < 4; i++)
            cpa16(base + dstA[i], (const char*)g_XH + aoff[i] + ko);
#pragma unroll
        for (int i = 0; i < 2; i++) {
            cpa16(base + 16384 + dstB[i], (const char*)g_W1H + boff[i] + ko);
            cpa16(base + 24576 + dstB[i], (const char*)g_W3H + boff[i] + ko);
        }
        cp_commit();
    };

    float c1[2][4][4], c3[2][4][4];
#pragma unroll
    for (int a = 0; a < 2; a++)
#pragma unroll
        for (int b = 0; b < 4; b++)
#pragma unroll
            for (int q = 0; q < 4; q++) { c1[a][b][q] = 0.0f; c3[a][b][q] = 0.0f; }

    int m0w = (wid & 3) * 32;
    int n0w = (wid >> 2) * 32;
    const int NC = DIM / 64;                    // 16

    load(0, 0); load(1, 1); load(2, 2);

#pragma unroll 1
    for (int c = 0; c < NC; c++) {
        cp_wait2();
        __syncthreads();
        int st = c % NSTG;
        uint32_t bA = smb + st * ST1;
#pragma unroll
        for (int ks = 0; ks < 4; ks++) {
            int k0b = ks * 32;
            uint32_t ah[2][4];
#pragma unroll
            for (int mg = 0; mg < 2; mg++) {
                int row = m0w + mg * 16 + (lane & 15);
                uint32_t off = SWZ((uint32_t)(row * 128 + k0b + (lane >> 4) * 16));
                ldm4(ah[mg], bA + off);
            }
#pragma unroll
            for (int g = 0; g < 2; g++) {
                int nrow = n0w + g * 16 + (lane & 7) + (lane >> 4) * 8;
                uint32_t bo = SWZ((uint32_t)(nrow * 128 + k0b + ((lane >> 3) & 1) * 16));
                uint32_t f1h[4], f3h[4];
                ldm4(f1h, bA + 16384 + bo);
                ldm4(f3h, bA + 24576 + bo);
#pragma unroll
                for (int mg = 0; mg < 2; mg++) {
#pragma unroll
                    for (int sub = 0; sub < 2; sub++) {
                        int ng = g * 2 + sub;
                        mma16816(c1[mg][ng], ah[mg], f1h + sub * 2);
                        mma16816(c3[mg][ng], ah[mg], f3h + sub * 2);
                    }
                }
            }
        }
        __syncthreads();
        if (c + NSTG < NC) load(c + NSTG, st);
        else cp_commit();
    }

    int goff = g_off[e];
    int t4 = lane >> 2, cpair = (lane & 3) * 2;
#pragma unroll
    for (int mg = 0; mg < 2; mg++) {
#pragma unroll
        for (int half = 0; half < 2; half++) {
            int mi = m0 + m0w + mg * 16 + half * 8 + t4;
            if (mi >= cnt) continue;
            size_t hb = (size_t)(goff + mi) * HP;
#pragma unroll
            for (int ng = 0; ng < 4; ng++) {
                int col = n0 + n0w + ng * 8 + cpair;
                float a0 = c1[mg][ng][half * 2 + 0];
                float a1 = c1[mg][ng][half * 2 + 1];
                float b0 = c3[mg][ng][half * 2 + 0];
                float b1 = c3[mg][ng][half * 2 + 1];
                float h0 = (a0 / (1.0f + __expf(-a0))) * b0;
                float h1 = (a1 / (1.0f + __expf(-a1))) * b1;
                *(uint32_t*)(g_HH + hb + col) = pkh(__float2half(h0), __float2half(h1));
            }
        }
    }
}

// ---------------- GEMM2: CTA 256x128, warp 64x64, fp16 1-pass ----------------
__global__ __launch_bounds__(256, 1) void gemm2_kernel(float* __restrict__ out) {
    int e = blockIdx.z;
    int cnt = g_count[e];
    int m0 = blockIdx.y * BM2;
    if (m0 >= cnt) return;
    int n0 = blockIdx.x * 128;

    extern __shared__ char smraw[];
    uint32_t smb = s2u(smraw);
    int tid = threadIdx.x, wid = tid >> 5, lane = tid & 31;
    int off_e = g_off[e];

    int rA = tid >> 3, c16 = tid & 7;
    uint32_t dstA[8], aoff[8];
#pragma unroll
    for (int i = 0; i < 8; i++) {
        int r = rA + 32 * i;
        dstA[i] = SWZ((uint32_t)(r * 128 + c16 * 16));
        int mi = m0 + r; if (mi >= cnt) mi = cnt - 1;
        aoff[i] = (uint32_t)(((off_e + mi) * HP + c16 * 8) * 2);
    }
    uint32_t dstB[4], boff[4];
#pragma unroll
    for (int i = 0; i < 4; i++) {
        int r = rA + 32 * i;
        dstB[i] = SWZ((uint32_t)(r * 128 + c16 * 16));
        boff[i] = (uint32_t)(((e * DIM + n0 + r) * HP + c16 * 8) * 2);
    }

    auto load = [&](int kc, int s) {
        uint32_t base = smb + s * ST2;
        uint32_t ko = (uint32_t)kc * 128;
#pragma unroll
        for (int i = 0; i < 8; i++)
            cpa16(base + dstA[i], (const char*)g_HH + aoff[i] + ko);
#pragma unroll
        for (int i = 0; i < 4; i++)
            cpa16(base + 32768 + dstB[i], (const char*)g_W2H + boff[i] + ko);
        cp_commit();
    };

    float cc[4][8][4];
#pragma unroll
    for (int a = 0; a < 4; a++)
#pragma unroll
        for (int b = 0; b < 8; b++)
#pragma unroll
            for (int q = 0; q < 4; q++) cc[a][b][q] = 0.0f;

    int m0w = (wid & 3) * 64;
    int n0w = (wid >> 2) * 64;
    const int NC = KH / 64;                     // 43

    load(0, 0); load(1, 1); load(2, 2);

#pragma unroll 1
    for (int c = 0; c < NC; c++) {
        cp_wait2();
        __syncthreads();
        int st = c % NSTG;
        uint32_t bA = smb + st * ST2;
#pragma unroll
        for (int ks = 0; ks < 4; ks++) {
            int k0b = ks * 32;
            uint32_t ah[4][4];
#pragma unroll
            for (int mg = 0; mg < 4; mg++) {
                int row = m0w + mg * 16 + (lane & 15);
                uint32_t off = SWZ((uint32_t)(row * 128 + k0b + (lane >> 4) * 16));
                ldm4(ah[mg], bA + off);
            }
#pragma unroll
            for (int g = 0; g < 4; g++) {
                int nrow = n0w + g * 16 + (lane & 7) + (lane >> 4) * 8;
                uint32_t bo = SWZ((uint32_t)(nrow * 128 + k0b + ((lane >> 3) & 1) * 16));
                uint32_t fh[4];
                ldm4(fh, bA + 32768 + bo);
#pragma unroll
                for (int mg = 0; mg < 4; mg++) {
#pragma unroll
                    for (int sub = 0; sub < 2; sub++) {
                        int ng = g * 2 + sub;
                        mma16816(cc[mg][ng], ah[mg], fh + sub * 2);
                    }
                }
            }
        }
        __syncthreads();
        if (c + NSTG < NC) load(c + NSTG, st);
        else cp_commit();
    }

    int t4 = lane >> 2, cpair = (lane & 3) * 2;
#pragma unroll
    for (int mg = 0; mg < 4; mg++) {
#pragma unroll
        for (int half = 0; half < 2; half++) {
            int mi = m0 + m0w + mg * 16 + half * 8 + t4;
            if (mi >= cnt) continue;
            int tok = g_tokens[e][mi];
            float wt = g_wts[e][mi];
            float* orow = out + (size_t)tok * DIM;
#pragma unroll
            for (int ng = 0; ng < 8; ng++) {
                int col = n0 + n0w + ng * 8 + cpair;
                redadd(&orow[col],     wt * cc[mg][ng][half * 2 + 0]);
                redadd(&orow[col + 1], wt * cc[mg][ng][half * 2 + 1]);
            }
        }
    }
}

// ---------------- launch (event-forked streams, capture-safe) ----------------
extern "C" void kernel_launch(void* const* d_in, const int* in_sizes, int n_in,
                              void* d_out, int out_size) {
    const float* x  = (const float*)d_in[0];
    const float* gw = (const float*)d_in[1];
    const float* w1 = (const float*)d_in[2];
    const float* w2 = (const float*)d_in[3];
    const float* w3 = (const float*)d_in[4];
    float* out = (float*)d_out;

    cudaFuncSetAttribute(gemm1_kernel, cudaFuncAttributeMaxDynamicSharedMemorySize, NSTG * ST1);
    cudaFuncSetAttribute(gemm2_kernel, cudaFuncAttributeMaxDynamicSharedMemorySize, NSTG * ST2);

    cudaStream_t s1, s2;
    cudaEvent_t evRoot, ev1, ev2;
    cudaStreamCreateWithFlags(&s1, cudaStreamNonBlocking);
    cudaStreamCreateWithFlags(&s2, cudaStreamNonBlocking);
    cudaEventCreateWithFlags(&evRoot, cudaEventDisableTiming);
    cudaEventCreateWithFlags(&ev1, cudaEventDisableTiming);
    cudaEventCreateWithFlags(&ev2, cudaEventDisableTiming);

    int nzero = out_size < TOKENS * DIM ? out_size : TOKENS * DIM;

    // fork
    cudaEventRecord(evRoot, 0);
    cudaStreamWaitEvent(s1, evRoot, 0);
    cudaStreamWaitEvent(s2, evRoot, 0);

    // base: routing chain (+x convert fused into router)
    reset_kernel<<<1, 32>>>();
    router_kernel<<<TOKENS * 32 / 256, 256>>>(x, gw);
    scan_kernel<<<1, 32>>>();
    aux_kernel<<<1, 32>>>(out, out_size);

    // s1: weight converts needed by gemm1
    convw13_kernel<<<(NE * HP * DIM / 4) / 256, 256, 0, s1>>>(w1, w3);
    cudaEventRecord(ev1, s1);

    // s2: only needed by gemm2
    zeroout_kernel<<<(nzero + 255) / 256, 256, 0, s2>>>(out, nzero);
    convw2_kernel<<<(NE * DIM * HP / 4) / 256, 256, 0, s2>>>(w2);
    cudaEventRecord(ev2, s2);

    // join s1 -> gemm1
    cudaStreamWaitEvent(0, ev1, 0);
    dim3 g1(KH / 64, TOKENS / BM1, NE);
    gemm1_kernel<<<g1, 256, NSTG * ST1>>>();

    // join s2 -> gemm2
    cudaStreamWaitEvent(0, ev2, 0);
    dim3 g2(DIM / 128, TOKENS / BM2, NE);
    gemm2_kernel<<<g2, 256, NSTG * ST2>>>(out);

    cudaEventDestroy(evRoot);
    cudaEventDestroy(ev1);
    cudaEventDestroy(ev2);
    cudaStreamDestroy(s1);
    cudaStreamDestroy(s2);
}